// round 14
// baseline (speedup 1.0000x reference)
#include <cuda_runtime.h>

namespace {
constexpr int kB   = 64;
constexpr int kN   = 883;
constexpr int kT   = 12;
constexpr int kTN  = 16;
constexpr int kTOD = 288;
constexpr int kP   = kB * kN;              // 56512 problems, 2 per warp
constexpr unsigned FM = 0xffffffffu;
} // namespace

__global__ void __launch_bounds__(256) mode_att_kernel(
    const float* __restrict__ enc,
    const int*   __restrict__ xm,
    const float* __restrict__ dec,
    const float* __restrict__ kb,
    const float* __restrict__ vb,
    const float* __restrict__ aw,
    const float* __restrict__ ab,
    float*       __restrict__ out)
{
    const int warp = (blockIdx.x * blockDim.x + threadIdx.x) >> 5;
    const int lane = threadIdx.x & 31;
    const int y    = lane & 15;

    // b-fastest remap: all 64 batches of one n run in adjacent warps so
    // duplicate-t K/V tiles hit L2 and aw/ab rows stay cache-hot.
    const int q = warp * 2 + (lane >> 4);      // linear problem id
    const int b = q & (kB - 1);                // kB = 64
    const int n = q >> 6;
    const int p = b * kN + n;                  // row index for enc/dec/out

    const int t = __ldg(xm + b * 2);           // x_mark_enc[b,0,0]

    const size_t rbase = ((size_t)((n * kTOD + t) * kTN + y)) * kT;
    const float* __restrict__ kr = kb + rbase;

    // Front batch: ONLY K and Q (keeps MLP_p1 small -> less cross-CTA
    // L1tex-queue spread per the B300 chip model). V is deferred.
    float4 k0 = *(const float4*)(kr);
    float4 k1 = *(const float4*)(kr + 4);
    float4 k2 = *(const float4*)(kr + 8);

    const float* __restrict__ qp = enc + (size_t)p * kT;
    float4 q0 = *(const float4*)(qp);
    float4 q1 = *(const float4*)(qp + 4);
    float4 q2 = *(const float4*)(qp + 8);

    // Per-key squared distance.
    float dd = 0.f, df;
    df = q0.x - k0.x; dd = fmaf(df, df, dd);
    df = q0.y - k0.y; dd = fmaf(df, df, dd);
    df = q0.z - k0.z; dd = fmaf(df, df, dd);
    df = q0.w - k0.w; dd = fmaf(df, df, dd);
    df = q1.x - k1.x; dd = fmaf(df, df, dd);
    df = q1.y - k1.y; dd = fmaf(df, df, dd);
    df = q1.z - k1.z; dd = fmaf(df, df, dd);
    df = q1.w - k1.w; dd = fmaf(df, df, dd);
    df = q2.x - k2.x; dd = fmaf(df, df, dd);
    df = q2.y - k2.y; dd = fmaf(df, df, dd);
    df = q2.z - k2.z; dd = fmaf(df, df, dd);
    df = q2.w - k2.w; dd = fmaf(df, df, dd);
    const float dist = sqrtf(dd);

    // Barrier: keep the V/aw/ab loads below from being hoisted into the
    // front batch (they are only needed after wave 1).
    asm volatile("" ::: "memory");

    // Deferred loads: V tile + gate weights. Their latency overlaps the
    // wave-1 shuffle chain and the MUFU stats block below.
    const float* __restrict__ vr = vb + rbase;
    float4 v0 = *(const float4*)(vr);
    float4 v1 = *(const float4*)(vr + 4);
    float4 v2 = *(const float4*)(vr + 8);

    const float* __restrict__ awp = aw + n * (kTN + 1);
    const float aw_y  = __ldg(awp + y);
    const float aw_16 = __ldg(awp + 16);
    const float bias  = __ldg(ab + n);

    // ---- reduction wave 1: Sum(d) and Sum(d^2), interleaved ----
    float s1 = dist, s2 = dd;
#pragma unroll
    for (int m = 8; m >= 1; m >>= 1) {
        s1 += __shfl_xor_sync(FM, s1, m, 16);
        s2 += __shfl_xor_sync(FM, s2, m, 16);
    }

    // First softmax stats (raw moments, ddof=1; |score| <= 37.5, no max-sub).
    const float mean = s1 * (1.0f / 16.0f);
    const float var  = fmaxf((s2 - s1 * mean) * (1.0f / 15.0f), 0.0f);
    const float istd = __fdividef(10.0f, sqrtf(var) + 1e-6f);
    const float ex   = __expf((mean - dist) * istd);

    // Second softmax stats over 17 keys (17th = Q+0.1, dist = sqrt(12*0.01)).
    const float d16    = 0.34641016151377545871f;
    const float s1b    = s1 + d16;
    const float mean17 = s1b * (1.0f / 17.0f);
    const float var17  = fmaxf((s2 + d16 * d16 - s1b * mean17) * (1.0f / 16.0f), 0.0f);
    const float istd2  = __fdividef(10.0f, sqrtf(var17) + 1e-6f);
    const float e2     = __expf((mean17 - dist) * istd2);
    const float e16    = __expf((mean17 - d16)  * istd2);

    // ---- wave 2: double-fold butterfly over 15 values {o[0..11], es, es2, ea} ----
    float es = ex, es2 = e2, ea = e2 * aw_y;
    float o[12];
    o[0] = ex * v0.x; o[1]  = ex * v0.y; o[2]  = ex * v0.z; o[3]  = ex * v0.w;
    o[4] = ex * v1.x; o[5]  = ex * v1.y; o[6]  = ex * v1.z; o[7]  = ex * v1.w;
    o[8] = ex * v2.x; o[9]  = ex * v2.y; o[10] = ex * v2.z; o[11] = ex * v2.w;

    // m=8 round on all 15.
    es  += __shfl_xor_sync(FM, es,  8, 16);
    es2 += __shfl_xor_sync(FM, es2, 8, 16);
    ea  += __shfl_xor_sync(FM, ea,  8, 16);
#pragma unroll
    for (int d = 0; d < 12; ++d)
        o[d] += __shfl_xor_sync(FM, o[d], 8, 16);

    // Fold 1 (bit 3 of y): low half keeps o[0..7]; high half {o[8..11], es, es2, ea}.
    const bool hi8 = (y & 8) != 0;
    float f[8];
    f[0] = hi8 ? o[8]  : o[0];
    f[1] = hi8 ? o[9]  : o[1];
    f[2] = hi8 ? o[10] : o[2];
    f[3] = hi8 ? o[11] : o[3];
    f[4] = hi8 ? es    : o[4];
    f[5] = hi8 ? es2   : o[5];
    f[6] = hi8 ? ea    : o[6];
    f[7] = hi8 ? 0.0f  : o[7];

    // m=4 round on 8.
#pragma unroll
    for (int d = 0; d < 8; ++d)
        f[d] += __shfl_xor_sync(FM, f[d], 4, 16);

    // Fold 2 (bit 2 of y): quads keep {o0-3}, {o4-7}, {o8-11}, {es,es2,ea,-}.
    const bool hi4 = (y & 4) != 0;
    float g[4];
    g[0] = hi4 ? f[4] : f[0];
    g[1] = hi4 ? f[5] : f[1];
    g[2] = hi4 ? f[6] : f[2];
    g[3] = hi4 ? f[7] : f[3];

    // m=2, m=1 rounds on 4.
#pragma unroll
    for (int m = 2; m >= 1; m >>= 1)
#pragma unroll
        for (int d = 0; d < 4; ++d)
            g[d] += __shfl_xor_sync(FM, g[d], m, 16);

    // Quad 3 (y=12..15) holds es=g[0], es2=g[1], ea=g[2]; compute gate there.
    const float inv2 = __fdividef(1.0f, g[1] + e16);
    float w   = (g[2] + e16 * aw_16) * inv2 + bias;
    float omw = (1.0f - w) * __fdividef(1.0f, g[0]);   // fold prob norm into blend
    w   = __shfl_sync(FM, w,   12, 16);
    omw = __shfl_sync(FM, omw, 12, 16);

    // ---- blend and write: lanes y=0,4,8 each write one float4 (4 dims) ----
    if ((y & 3) == 0 && y < 12) {
        const size_t base = (size_t)p * kT + y;   // y in {0,4,8}
        float4 d4 = *(const float4*)(dec + base);
        float4 r4 = make_float4(fmaf(omw, g[0], w * d4.x),
                                fmaf(omw, g[1], w * d4.y),
                                fmaf(omw, g[2], w * d4.z),
                                fmaf(omw, g[3], w * d4.w));
        *(float4*)(out + base) = r4;
    }
}

extern "C" void kernel_launch(void* const* d_in, const int* in_sizes, int n_in,
                              void* d_out, int out_size) {
    const float* enc = (const float*)d_in[0];
    const int*   xm  = (const int*)  d_in[1];
    const float* dec = (const float*)d_in[2];
    const float* kb  = (const float*)d_in[3];
    const float* vb  = (const float*)d_in[4];
    const float* aw  = (const float*)d_in[5];
    const float* ab  = (const float*)d_in[6];
    float*       out = (float*)d_out;

    const int problems_per_block = 16;            // 8 warps * 2
    const int blocks = kP / problems_per_block;   // 3532 (exact)
    mode_att_kernel<<<blocks, 256>>>(enc, xm, dec, kb, vb, aw, ab, out);
}

// round 15
// speedup vs baseline: 1.0171x; 1.0171x over previous
#include <cuda_runtime.h>

namespace {
constexpr int kB   = 64;
constexpr int kN   = 883;
constexpr int kT   = 12;
constexpr int kTN  = 16;
constexpr int kTOD = 288;
constexpr int kP   = kB * kN;              // 56512 problems, 2 per warp
constexpr unsigned FM = 0xffffffffu;
} // namespace

__global__ void __launch_bounds__(256) mode_att_kernel(
    const float* __restrict__ enc,
    const int*   __restrict__ xm,
    const float* __restrict__ dec,
    const float* __restrict__ kb,
    const float* __restrict__ vb,
    const float* __restrict__ aw,
    const float* __restrict__ ab,
    float*       __restrict__ out)
{
    const int warp = (blockIdx.x * blockDim.x + threadIdx.x) >> 5;
    const int lane = threadIdx.x & 31;
    const int y    = lane & 15;

    // b-fastest remap: all 64 batches of one n run in adjacent warps so
    // duplicate-t K/V tiles hit L2 and aw/ab rows stay cache-hot.
    const int q = warp * 2 + (lane >> 4);      // linear problem id
    const int b = q & (kB - 1);                // kB = 64
    const int n = q >> 6;
    const int p = b * kN + n;                  // row index for enc/dec/out

    const int t = __ldg(xm + b * 2);           // x_mark_enc[b,0,0]

    const size_t rbase = ((size_t)((n * kTOD + t) * kTN + y)) * kT;
    const float* __restrict__ kr = kb + rbase;
    const float* __restrict__ vr = vb + rbase;

    // Front-batched loads for MLP. K/V: default policy (L2 reuse across b).
    float4 k0 = *(const float4*)(kr);
    float4 k1 = *(const float4*)(kr + 4);
    float4 k2 = *(const float4*)(kr + 8);
    float4 v0 = *(const float4*)(vr);
    float4 v1 = *(const float4*)(vr + 4);
    float4 v2 = *(const float4*)(vr + 8);

    // enc: single-use stream -> evict-first so it doesn't displace K/V in L2.
    const float* __restrict__ qp = enc + (size_t)p * kT;
    float4 q0 = __ldcs((const float4*)(qp));
    float4 q1 = __ldcs((const float4*)(qp + 4));
    float4 q2 = __ldcs((const float4*)(qp + 8));

    const float* __restrict__ awp = aw + n * (kTN + 1);
    const float aw_y  = __ldg(awp + y);
    const float aw_16 = __ldg(awp + 16);
    const float bias  = __ldg(ab + n);

    // Per-key squared distance.
    float dd = 0.f, df;
    df = q0.x - k0.x; dd = fmaf(df, df, dd);
    df = q0.y - k0.y; dd = fmaf(df, df, dd);
    df = q0.z - k0.z; dd = fmaf(df, df, dd);
    df = q0.w - k0.w; dd = fmaf(df, df, dd);
    df = q1.x - k1.x; dd = fmaf(df, df, dd);
    df = q1.y - k1.y; dd = fmaf(df, df, dd);
    df = q1.z - k1.z; dd = fmaf(df, df, dd);
    df = q1.w - k1.w; dd = fmaf(df, df, dd);
    df = q2.x - k2.x; dd = fmaf(df, df, dd);
    df = q2.y - k2.y; dd = fmaf(df, df, dd);
    df = q2.z - k2.z; dd = fmaf(df, df, dd);
    df = q2.w - k2.w; dd = fmaf(df, df, dd);
    const float dist = sqrtf(dd);

    // ---- reduction wave 1: Sum(d) and Sum(d^2), interleaved ----
    float s1 = dist, s2 = dd;
#pragma unroll
    for (int m = 8; m >= 1; m >>= 1) {
        s1 += __shfl_xor_sync(FM, s1, m, 16);
        s2 += __shfl_xor_sync(FM, s2, m, 16);
    }

    // First softmax stats (raw moments, ddof=1; |score| <= 37.5, no max-sub).
    const float mean = s1 * (1.0f / 16.0f);
    const float var  = fmaxf((s2 - s1 * mean) * (1.0f / 15.0f), 0.0f);
    const float istd = __fdividef(10.0f, sqrtf(var) + 1e-6f);
    const float ex   = __expf((mean - dist) * istd);

    // Second softmax stats over 17 keys (17th = Q+0.1, dist = sqrt(12*0.01)).
    const float d16    = 0.34641016151377545871f;
    const float s1b    = s1 + d16;
    const float mean17 = s1b * (1.0f / 17.0f);
    const float var17  = fmaxf((s2 + d16 * d16 - s1b * mean17) * (1.0f / 16.0f), 0.0f);
    const float istd2  = __fdividef(10.0f, sqrtf(var17) + 1e-6f);
    const float e2     = __expf((mean17 - dist) * istd2);
    const float e16    = __expf((mean17 - d16)  * istd2);

    // ---- wave 2: double-fold butterfly over 15 values {o[0..11], es, es2, ea} ----
    float es = ex, es2 = e2, ea = e2 * aw_y;
    float o[12];
    o[0] = ex * v0.x; o[1]  = ex * v0.y; o[2]  = ex * v0.z; o[3]  = ex * v0.w;
    o[4] = ex * v1.x; o[5]  = ex * v1.y; o[6]  = ex * v1.z; o[7]  = ex * v1.w;
    o[8] = ex * v2.x; o[9]  = ex * v2.y; o[10] = ex * v2.z; o[11] = ex * v2.w;

    // m=8 round on all 15.
    es  += __shfl_xor_sync(FM, es,  8, 16);
    es2 += __shfl_xor_sync(FM, es2, 8, 16);
    ea  += __shfl_xor_sync(FM, ea,  8, 16);
#pragma unroll
    for (int d = 0; d < 12; ++d)
        o[d] += __shfl_xor_sync(FM, o[d], 8, 16);

    // Fold 1 (bit 3 of y): low half keeps o[0..7]; high half {o[8..11], es, es2, ea}.
    const bool hi8 = (y & 8) != 0;
    float f[8];
    f[0] = hi8 ? o[8]  : o[0];
    f[1] = hi8 ? o[9]  : o[1];
    f[2] = hi8 ? o[10] : o[2];
    f[3] = hi8 ? o[11] : o[3];
    f[4] = hi8 ? es    : o[4];
    f[5] = hi8 ? es2   : o[5];
    f[6] = hi8 ? ea    : o[6];
    f[7] = hi8 ? 0.0f  : o[7];

    // m=4 round on 8.
#pragma unroll
    for (int d = 0; d < 8; ++d)
        f[d] += __shfl_xor_sync(FM, f[d], 4, 16);

    // Fold 2 (bit 2 of y): quads keep {o0-3}, {o4-7}, {o8-11}, {es,es2,ea,-}.
    const bool hi4 = (y & 4) != 0;
    float g[4];
    g[0] = hi4 ? f[4] : f[0];
    g[1] = hi4 ? f[5] : f[1];
    g[2] = hi4 ? f[6] : f[2];
    g[3] = hi4 ? f[7] : f[3];

    // m=2, m=1 rounds on 4.
#pragma unroll
    for (int m = 2; m >= 1; m >>= 1)
#pragma unroll
        for (int d = 0; d < 4; ++d)
            g[d] += __shfl_xor_sync(FM, g[d], m, 16);

    // Quad 3 (y=12..15) holds es=g[0], es2=g[1], ea=g[2]; compute gate there.
    const float inv2 = __fdividef(1.0f, g[1] + e16);
    float w   = (g[2] + e16 * aw_16) * inv2 + bias;
    float omw = (1.0f - w) * __fdividef(1.0f, g[0]);   // fold prob norm into blend
    w   = __shfl_sync(FM, w,   12, 16);
    omw = __shfl_sync(FM, omw, 12, 16);

    // ---- blend and write: lanes y=0,4,8 each write one float4 (4 dims) ----
    // dec/out: single-use streams -> evict-first.
    if ((y & 3) == 0 && y < 12) {
        const size_t base = (size_t)p * kT + y;   // y in {0,4,8}
        float4 d4 = __ldcs((const float4*)(dec + base));
        float4 r4 = make_float4(fmaf(omw, g[0], w * d4.x),
                                fmaf(omw, g[1], w * d4.y),
                                fmaf(omw, g[2], w * d4.z),
                                fmaf(omw, g[3], w * d4.w));
        __stcs((float4*)(out + base), r4);
    }
}

extern "C" void kernel_launch(void* const* d_in, const int* in_sizes, int n_in,
                              void* d_out, int out_size) {
    const float* enc = (const float*)d_in[0];
    const int*   xm  = (const int*)  d_in[1];
    const float* dec = (const float*)d_in[2];
    const float* kb  = (const float*)d_in[3];
    const float* vb  = (const float*)d_in[4];
    const float* aw  = (const float*)d_in[5];
    const float* ab  = (const float*)d_in[6];
    float*       out = (float*)d_out;

    const int problems_per_block = 16;            // 8 warps * 2
    const int blocks = kP / problems_per_block;   // 3532 (exact)
    mode_att_kernel<<<blocks, 256>>>(enc, xm, dec, kb, vb, aw, ab, out);
}